// round 9
// baseline (speedup 1.0000x reference)
#include <cuda_runtime.h>
#include <math.h>
#include <stdint.h>

#define BB 4
#define TT 2048
#define CC 1024
#define NH 16
#define HD 64
#define BT (BB*TT)      // 8192
#define C3 (3*CC)       // 3072

// Scratch (device globals; no allocation allowed)
__device__ float g_qkv[BT * C3];   // [BT, 3C]
__device__ float g_q[BT * CC];     // [B,H,T,64]
__device__ float g_k[BT * CC];
__device__ float g_v[BT * CC];
__device__ float g_attn[BT * CC];  // [B,T,C]

// ---------------------------------------------------------------------------
// helpers
// ---------------------------------------------------------------------------
__device__ __forceinline__ unsigned f2tf(float x) {
    unsigned r;
    asm("cvt.rna.tf32.f32 %0, %1;" : "=r"(r) : "f"(x));
    return r;
}

// D = A(16x8) * B(8x8) + D  (tf32 in, fp32 accum), row.col
__device__ __forceinline__ void mma8(float* c, const unsigned* a,
                                     unsigned b0, unsigned b1) {
    asm("mma.sync.aligned.m16n8k8.row.col.f32.tf32.tf32.f32 "
        "{%0,%1,%2,%3}, {%4,%5,%6,%7}, {%8,%9}, {%0,%1,%2,%3};"
        : "+f"(c[0]), "+f"(c[1]), "+f"(c[2]), "+f"(c[3])
        : "r"(a[0]), "r"(a[1]), "r"(a[2]), "r"(a[3]), "r"(b0), "r"(b1));
}

// ---------------------------------------------------------------------------
// tf32 tensor-core GEMM v2: CTA tile 128x256xK16, 8 warps in 2(m) x 4(n),
// warp tile 64x64 (4x8 m16n8 tiles). A-fragments reused across 8 n-tiles:
// smem fragment bytes/FLOP ~1.5x lower than the 64x32 version (the measured
// bottleneck). Register-prefetch of the next k-tile overlaps LDG with MMAs
// (needed: 1 CTA/SM at these register counts).
// As: [k][m] stride 136, m XOR-swizzled by 8*((k>>2)&3)  -> conflict-free
// Bs: [k][n] stride 264 (== 8 mod 32, same bank math)    -> conflict-free
// Requires M%128==0, N%256==0, K%16==0.
// ---------------------------------------------------------------------------
__global__ __launch_bounds__(256) void gemm_tf32(
    const float* __restrict__ A, const float* __restrict__ Bm,
    float* __restrict__ Cm, int M, int N, int K)
{
    __shared__ unsigned As[16 * 136];
    __shared__ unsigned Bs[16 * 264];

    int tid = threadIdx.x;
    int lane = tid & 31;
    int warp = tid >> 5;
    int gid = lane >> 2, tig = lane & 3;
    int warp_m = warp >> 2, warp_n = warp & 3;
    int bm = blockIdx.y, bn = blockIdx.x;

    const float* Abase = A + (size_t)(bm * 128) * K;
    const float* Bbase = Bm + (size_t)bn * 256;

    float acc[4][8][4];
    #pragma unroll
    for (int mt = 0; mt < 4; mt++)
        #pragma unroll
        for (int nt = 0; nt < 8; nt++)
            #pragma unroll
            for (int e = 0; e < 4; e++) acc[mt][nt][e] = 0.f;

    int am = tid >> 2;            // 0..63
    int af4 = tid & 3;            // k-group
    int bk = tid >> 5;            // 0..7
    int bc4 = (tid & 31) * 4;     // 0..124

    // preload tile 0
    float4 a0v = *(const float4*)(Abase + (size_t)am * K + af4 * 4);
    float4 a1v = *(const float4*)(Abase + (size_t)(am + 64) * K + af4 * 4);
    float4 b00 = *(const float4*)(Bbase + (size_t)bk * N + bc4);
    float4 b01 = *(const float4*)(Bbase + (size_t)bk * N + 128 + bc4);
    float4 b10 = *(const float4*)(Bbase + (size_t)(bk + 8) * N + bc4);
    float4 b11 = *(const float4*)(Bbase + (size_t)(bk + 8) * N + 128 + bc4);

    for (int k0 = 0; k0 < K; k0 += 16) {
        __syncthreads();   // previous compute done with smem
        {
            int swz = 8 * af4;
            int kb4 = af4 * 4;
            As[(kb4 + 0) * 136 + (am ^ swz)] = f2tf(a0v.x);
            As[(kb4 + 1) * 136 + (am ^ swz)] = f2tf(a0v.y);
            As[(kb4 + 2) * 136 + (am ^ swz)] = f2tf(a0v.z);
            As[(kb4 + 3) * 136 + (am ^ swz)] = f2tf(a0v.w);
            int am2 = am + 64;
            As[(kb4 + 0) * 136 + (am2 ^ swz)] = f2tf(a1v.x);
            As[(kb4 + 1) * 136 + (am2 ^ swz)] = f2tf(a1v.y);
            As[(kb4 + 2) * 136 + (am2 ^ swz)] = f2tf(a1v.z);
            As[(kb4 + 3) * 136 + (am2 ^ swz)] = f2tf(a1v.w);

            uint4 t;
            t = make_uint4(f2tf(b00.x), f2tf(b00.y), f2tf(b00.z), f2tf(b00.w));
            *(uint4*)&Bs[bk * 264 + bc4] = t;
            t = make_uint4(f2tf(b01.x), f2tf(b01.y), f2tf(b01.z), f2tf(b01.w));
            *(uint4*)&Bs[bk * 264 + 128 + bc4] = t;
            t = make_uint4(f2tf(b10.x), f2tf(b10.y), f2tf(b10.z), f2tf(b10.w));
            *(uint4*)&Bs[(bk + 8) * 264 + bc4] = t;
            t = make_uint4(f2tf(b11.x), f2tf(b11.y), f2tf(b11.z), f2tf(b11.w));
            *(uint4*)&Bs[(bk + 8) * 264 + 128 + bc4] = t;
        }
        __syncthreads();

        // prefetch next tile (overlaps the MMA block below)
        if (k0 + 16 < K) {
            int kn = k0 + 16;
            a0v = *(const float4*)(Abase + (size_t)am * K + kn + af4 * 4);
            a1v = *(const float4*)(Abase + (size_t)(am + 64) * K + kn + af4 * 4);
            b00 = *(const float4*)(Bbase + (size_t)(kn + bk) * N + bc4);
            b01 = *(const float4*)(Bbase + (size_t)(kn + bk) * N + 128 + bc4);
            b10 = *(const float4*)(Bbase + (size_t)(kn + bk + 8) * N + bc4);
            b11 = *(const float4*)(Bbase + (size_t)(kn + bk + 8) * N + 128 + bc4);
        }

        #pragma unroll
        for (int ks = 0; ks < 16; ks += 8) {
            unsigned afr[4][4];
            unsigned bfr[8][2];
            int swz1 = 8 * ((ks >> 2) & 3);
            int swz2 = 8 * (((ks + 4) >> 2) & 3);
            #pragma unroll
            for (int mt = 0; mt < 4; mt++) {
                int m = warp_m * 64 + mt * 16 + gid;
                afr[mt][0] = As[(ks + tig) * 136 + (m ^ swz1)];
                afr[mt][1] = As[(ks + tig) * 136 + ((m + 8) ^ swz1)];
                afr[mt][2] = As[(ks + tig + 4) * 136 + (m ^ swz2)];
                afr[mt][3] = As[(ks + tig + 4) * 136 + ((m + 8) ^ swz2)];
            }
            #pragma unroll
            for (int nt = 0; nt < 8; nt++) {
                int n = warp_n * 64 + nt * 8 + gid;
                bfr[nt][0] = Bs[(ks + tig) * 264 + n];
                bfr[nt][1] = Bs[(ks + tig + 4) * 264 + n];
            }
            #pragma unroll
            for (int mt = 0; mt < 4; mt++)
                #pragma unroll
                for (int nt = 0; nt < 8; nt++)
                    mma8(acc[mt][nt], afr[mt], bfr[nt][0], bfr[nt][1]);
        }
    }

    #pragma unroll
    for (int mt = 0; mt < 4; mt++)
        #pragma unroll
        for (int nt = 0; nt < 8; nt++) {
            int row = bm * 128 + warp_m * 64 + mt * 16 + gid;
            int col = bn * 256 + warp_n * 64 + nt * 8 + tig * 2;
            *(float2*)&Cm[(size_t)row * N + col] =
                make_float2(acc[mt][nt][0], acc[mt][nt][1]);
            *(float2*)&Cm[(size_t)(row + 8) * N + col] =
                make_float2(acc[mt][nt][2], acc[mt][nt][3]);
        }
}

// ---------------------------------------------------------------------------
// Split qkv -> q,k,v in [B,H,T,64] layout; apply RoPE to q,k. (R4 version)
// ---------------------------------------------------------------------------
__global__ void rope_split_kernel()
{
    int idx = blockIdx.x * blockDim.x + threadIdx.x;
    const int total = BB * NH * TT * 32;
    if (idx >= total) return;

    int jj = idx & 31;
    int tmp = idx >> 5;
    int t = tmp & (TT - 1);
    tmp >>= 11;
    int h = tmp & (NH - 1);
    int b = tmp >> 4;

    const float LOG1E4 = 9.210340371976184f;
    float inv_freq = expf(-(float)jj * (LOG1E4 / 32.0f));
    float ang = (float)t * inv_freq;
    float cs = cosf(ang), sn = sinf(ang);

    size_t src_row = (size_t)(b * TT + t) * C3;
    int col = h * HD + jj;

    float q1 = g_qkv[src_row + col];
    float q2 = g_qkv[src_row + col + 32];
    float k1 = g_qkv[src_row + CC + col];
    float k2 = g_qkv[src_row + CC + col + 32];
    float v1 = g_qkv[src_row + 2 * CC + col];
    float v2 = g_qkv[src_row + 2 * CC + col + 32];

    size_t dst = ((size_t)(b * NH + h) * TT + t) * HD + jj;
    g_q[dst]      = q1 * cs - q2 * sn;
    g_q[dst + 32] = q2 * cs + q1 * sn;
    g_k[dst]      = k1 * cs - k2 * sn;
    g_k[dst + 32] = k2 * cs + k1 * sn;
    g_v[dst]      = v1;
    g_v[dst + 32] = v2;
}

// ---------------------------------------------------------------------------
// Flash attention (causal) on tensor cores, tf32 mma — exact R4 kernel.
// CTA = 128 queries x kv-tiles of 64, one (b,h). 8 warps.
// Smem (uint32):
//   sQ [64][136]  (d, q)     tf32, Q pre-scaled by 0.125
//   sP [64][136]  (kv, q)    tf32
//   sK [64][72]   (d, kv^swz(d))
//   sV [64][72]   (kv, d^swz(kv))     swz(i) = ((i>>2)&7)<<2
// ---------------------------------------------------------------------------
#define AQ_STR 136
#define AK_STR 72
#define ATTN_SMEM_WORDS (2 * 64 * AQ_STR + 2 * 64 * AK_STR)

__global__ __launch_bounds__(256) void attn_mma_kernel()
{
    extern __shared__ unsigned sm[];
    unsigned* sQ = sm;
    unsigned* sP = sm + 64 * AQ_STR;
    unsigned* sK = sm + 2 * 64 * AQ_STR;
    unsigned* sV = sK + 64 * AK_STR;

    int tid = threadIdx.x;
    int lane = tid & 31;
    int warp = tid >> 5;
    int gid = lane >> 2, tig = lane & 3;
    int qb = blockIdx.x;       // query block 0..15
    int bh = blockIdx.y;       // b*NH + h

    const float* Qg = g_q + ((size_t)bh * TT + qb * 128) * HD;
    const float* Kg = g_k + (size_t)bh * TT * HD;
    const float* Vg = g_v + (size_t)bh * TT * HD;

    // load Q (128x64) -> sQ[d][q], tf32, fold in 1/8 scale
    #pragma unroll
    for (int it = 0; it < 8; it++) {
        int fid = tid + 256 * it;
        int q = fid >> 4;
        int d0 = (fid & 15) * 4;
        float4 v = *(const float4*)(Qg + q * 64 + d0);
        sQ[(d0 + 0) * AQ_STR + q] = f2tf(v.x * 0.125f);
        sQ[(d0 + 1) * AQ_STR + q] = f2tf(v.y * 0.125f);
        sQ[(d0 + 2) * AQ_STR + q] = f2tf(v.z * 0.125f);
        sQ[(d0 + 3) * AQ_STR + q] = f2tf(v.w * 0.125f);
    }

    float oacc[8][4];
    #pragma unroll
    for (int nt = 0; nt < 8; nt++)
        #pragma unroll
        for (int e = 0; e < 4; e++) oacc[nt][e] = 0.f;
    float rm0 = -1e30f, rm1 = -1e30f, rl0 = 0.f, rl1 = 0.f;

    int m_local = warp * 16 + gid;           // query row (local), +8 for second
    int row1 = qb * 128 + m_local;           // global query rows
    int row2 = row1 + 8;

    int kb_max = 2 * qb + 1;
    for (int kb = 0; kb <= kb_max; kb++) {
        __syncthreads();
        // load K,V tile (64x64) with transpose/swizzle
        #pragma unroll
        for (int it = 0; it < 4; it++) {
            int fid = tid + 256 * it;
            int r = fid >> 4;                // kv row
            int d0 = (fid & 15) * 4;
            const float* kp = Kg + (size_t)(kb * 64 + r) * 64 + d0;
            float4 kv4 = *(const float4*)kp;
            sK[(d0 + 0) * AK_STR + (r ^ ((((d0 + 0) >> 2) & 7) << 2))] = f2tf(kv4.x);
            sK[(d0 + 1) * AK_STR + (r ^ ((((d0 + 1) >> 2) & 7) << 2))] = f2tf(kv4.y);
            sK[(d0 + 2) * AK_STR + (r ^ ((((d0 + 2) >> 2) & 7) << 2))] = f2tf(kv4.z);
            sK[(d0 + 3) * AK_STR + (r ^ ((((d0 + 3) >> 2) & 7) << 2))] = f2tf(kv4.w);
            const float* vp = Vg + (size_t)(kb * 64 + r) * 64 + d0;
            float4 vv4 = *(const float4*)vp;
            int swzr = ((r >> 2) & 7) << 2;
            uint4 tv = make_uint4(f2tf(vv4.x), f2tf(vv4.y), f2tf(vv4.z), f2tf(vv4.w));
            *(uint4*)&sV[r * AK_STR + (d0 ^ swzr)] = tv;
        }
        __syncthreads();

        // S = Q K^T for my 16-row strip (16 x 64)
        float sacc[8][4];
        #pragma unroll
        for (int nt = 0; nt < 8; nt++)
            #pragma unroll
            for (int e = 0; e < 4; e++) sacc[nt][e] = 0.f;

        #pragma unroll
        for (int ks = 0; ks < 64; ks += 8) {
            unsigned a[4];
            a[0] = sQ[(ks + tig) * AQ_STR + m_local];
            a[1] = sQ[(ks + tig) * AQ_STR + m_local + 8];
            a[2] = sQ[(ks + tig + 4) * AQ_STR + m_local];
            a[3] = sQ[(ks + tig + 4) * AQ_STR + m_local + 8];
            int c1 = ((ks >> 2) & 7) << 2;
            int c2 = (((ks + 4) >> 2) & 7) << 2;
            #pragma unroll
            for (int nt = 0; nt < 8; nt++) {
                int n = nt * 8 + gid;
                unsigned b0 = sK[(ks + tig) * AK_STR + (n ^ c1)];
                unsigned b1 = sK[(ks + tig + 4) * AK_STR + (n ^ c2)];
                mma8(sacc[nt], a, b0, b1);
            }
        }

        // causal mask (only the two diagonal-straddling tiles need it)
        if (kb >= 2 * qb) {
            #pragma unroll
            for (int nt = 0; nt < 8; nt++) {
                int colb = kb * 64 + nt * 8 + tig * 2;
                if (colb + 0 > row1) sacc[nt][0] = -1e30f;
                if (colb + 1 > row1) sacc[nt][1] = -1e30f;
                if (colb + 0 > row2) sacc[nt][2] = -1e30f;
                if (colb + 1 > row2) sacc[nt][3] = -1e30f;
            }
        }

        // online softmax (quad = 4 lanes covering one row)
        float mx0 = -1e30f, mx1 = -1e30f;
        #pragma unroll
        for (int nt = 0; nt < 8; nt++) {
            mx0 = fmaxf(mx0, fmaxf(sacc[nt][0], sacc[nt][1]));
            mx1 = fmaxf(mx1, fmaxf(sacc[nt][2], sacc[nt][3]));
        }
        mx0 = fmaxf(mx0, __shfl_xor_sync(0xffffffffu, mx0, 1));
        mx0 = fmaxf(mx0, __shfl_xor_sync(0xffffffffu, mx0, 2));
        mx1 = fmaxf(mx1, __shfl_xor_sync(0xffffffffu, mx1, 1));
        mx1 = fmaxf(mx1, __shfl_xor_sync(0xffffffffu, mx1, 2));

        float mn0 = fmaxf(rm0, mx0);
        float mn1 = fmaxf(rm1, mx1);
        float corr0 = __expf(rm0 - mn0);
        float corr1 = __expf(rm1 - mn1);
        rm0 = mn0; rm1 = mn1;

        float sum0 = 0.f, sum1 = 0.f;
        #pragma unroll
        for (int nt = 0; nt < 8; nt++) {
            sacc[nt][0] = __expf(sacc[nt][0] - mn0);
            sacc[nt][1] = __expf(sacc[nt][1] - mn0);
            sacc[nt][2] = __expf(sacc[nt][2] - mn1);
            sacc[nt][3] = __expf(sacc[nt][3] - mn1);
            sum0 += sacc[nt][0] + sacc[nt][1];
            sum1 += sacc[nt][2] + sacc[nt][3];
        }
        sum0 += __shfl_xor_sync(0xffffffffu, sum0, 1);
        sum0 += __shfl_xor_sync(0xffffffffu, sum0, 2);
        sum1 += __shfl_xor_sync(0xffffffffu, sum1, 1);
        sum1 += __shfl_xor_sync(0xffffffffu, sum1, 2);
        rl0 = rl0 * corr0 + sum0;
        rl1 = rl1 * corr1 + sum1;

        #pragma unroll
        for (int nt = 0; nt < 8; nt++) {
            oacc[nt][0] *= corr0; oacc[nt][1] *= corr0;
            oacc[nt][2] *= corr1; oacc[nt][3] *= corr1;
        }

        // publish P -> sP[kv][q] (tf32)
        #pragma unroll
        for (int nt = 0; nt < 8; nt++) {
            int kvc = nt * 8 + tig * 2;
            sP[(kvc + 0) * AQ_STR + m_local]     = f2tf(sacc[nt][0]);
            sP[(kvc + 1) * AQ_STR + m_local]     = f2tf(sacc[nt][1]);
            sP[(kvc + 0) * AQ_STR + m_local + 8] = f2tf(sacc[nt][2]);
            sP[(kvc + 1) * AQ_STR + m_local + 8] = f2tf(sacc[nt][3]);
        }
        __syncthreads();

        // O += P @ V   (16 x 64) += (16 x 64)(64 x 64)
        #pragma unroll
        for (int ks = 0; ks < 64; ks += 8) {
            unsigned a[4];
            a[0] = sP[(ks + tig) * AQ_STR + m_local];
            a[1] = sP[(ks + tig) * AQ_STR + m_local + 8];
            a[2] = sP[(ks + tig + 4) * AQ_STR + m_local];
            a[3] = sP[(ks + tig + 4) * AQ_STR + m_local + 8];
            int c1 = ((ks >> 2) & 7) << 2;
            int c2 = (((ks + 4) >> 2) & 7) << 2;
            #pragma unroll
            for (int nt = 0; nt < 8; nt++) {
                int n = nt * 8 + gid;
                unsigned b0 = sV[(ks + tig) * AK_STR + (n ^ c1)];
                unsigned b1 = sV[(ks + tig + 4) * AK_STR + (n ^ c2)];
                mma8(oacc[nt], a, b0, b1);
            }
        }
    }

    // epilogue: normalize, write to [B,T,C]
    int b = bh >> 4;
    int h = bh & (NH - 1);
    float il0 = 1.f / rl0;
    float il1 = 1.f / rl1;
    #pragma unroll
    for (int nt = 0; nt < 8; nt++) {
        int d = nt * 8 + tig * 2;
        *(float2*)&g_attn[((size_t)(b * TT + row1)) * CC + h * 64 + d] =
            make_float2(oacc[nt][0] * il0, oacc[nt][1] * il0);
        *(float2*)&g_attn[((size_t)(b * TT + row2)) * CC + h * 64 + d] =
            make_float2(oacc[nt][2] * il1, oacc[nt][3] * il1);
    }
}

// ---------------------------------------------------------------------------
extern "C" void kernel_launch(void* const* d_in, const int* in_sizes, int n_in,
                              void* d_out, int out_size)
{
    const float* x     = (const float*)d_in[0];
    const float* w_qkv = (const float*)d_in[1];
    const float* w_out = (const float*)d_in[2];
    float* out = (float*)d_out;

    float *qkv_p, *attn_p;
    cudaGetSymbolAddress((void**)&qkv_p,  g_qkv);
    cudaGetSymbolAddress((void**)&attn_p, g_attn);

    // 1) QKV projection: [8192,1024] @ [1024,3072]   (N tile 256)
    {
        dim3 grid(C3 / 256, BT / 128);
        gemm_tf32<<<grid, 256>>>(x, w_qkv, qkv_p, BT, C3, CC);
    }

    // 2) split + RoPE
    {
        int total = BB * NH * TT * 32;
        rope_split_kernel<<<(total + 255) / 256, 256>>>();
    }

    // 3) flash attention (tensor cores)
    {
        int smem_bytes = ATTN_SMEM_WORDS * sizeof(unsigned);
        cudaFuncSetAttribute(attn_mma_kernel,
                             cudaFuncAttributeMaxDynamicSharedMemorySize,
                             smem_bytes);
        dim3 grid(TT / 128, BB * NH);
        attn_mma_kernel<<<grid, 256, smem_bytes>>>();
    }

    // 4) output projection: [8192,1024] @ [1024,1024]   (N tile 256)
    {
        dim3 grid(CC / 256, BT / 128);
        gemm_tf32<<<grid, 256>>>(attn_p, w_out, out, BT, CC, CC);
    }
}